// round 7
// baseline (speedup 1.0000x reference)
#include <cuda_runtime.h>

#define H_LR 512
#define W_LR 512
#define H_HR 2048
#define W_HR 2048
#define PLANES 12
#define EPS_F 0.01f

// Scratch for mean_A / mean_b at low resolution (alloc-free: __device__ globals)
__device__ float g_meanA[PLANES * H_LR * W_LR];
__device__ float g_meanB[PLANES * H_LR * W_LR];

#define TILE 32
#define SM_W 36   // TILE + 4 (2-pixel halo each side for double 3x3)
#define SM_A 34   // TILE + 2 (1-pixel apron of A/b)
#define SSTR 37   // row stride

__global__ __launch_bounds__(256)
void k1_ab_mean(const float* __restrict__ x, const float* __restrict__ y) {
    __shared__ float sx[SM_W * SSTR];
    __shared__ float sy[SM_W * SSTR];
    __shared__ float sA[SM_A * SSTR];
    __shared__ float sB[SM_A * SSTR];

    const int plane = blockIdx.z;
    const int gy0 = blockIdx.y * TILE;
    const int gx0 = blockIdx.x * TILE;
    const float* __restrict__ xp = x + (size_t)plane * (H_LR * W_LR);
    const float* __restrict__ yp = y + (size_t)plane * (H_LR * W_LR);
    const int t = threadIdx.y * 32 + threadIdx.x;
    const float inv9 = 1.0f / 9.0f;

    // Phase 1: load 36x36 halo with edge clamp
    for (int idx = t; idx < SM_W * SM_W; idx += 256) {
        int i = idx / SM_W, j = idx - i * SM_W;
        int gy = min(max(gy0 - 2 + i, 0), H_LR - 1);
        int gx = min(max(gx0 - 2 + j, 0), W_LR - 1);
        sx[i * SSTR + j] = xp[gy * W_LR + gx];
        sy[i * SSTR + j] = yp[gy * W_LR + gx];
    }
    __syncthreads();

    // Phase 2: compute A,b on the 34x34 apron. TWO outputs per thread paired
    // VERTICALLY (apron rows 2p, 2p+1) so consecutive threads touch
    // consecutive smem columns -> conflict-free LDS. The two 3x3 windows
    // share 2 tap rows (4 distinct rows total). A/b are evaluated at CLAMPED
    // global pixel coords (== replication padding of A for boxfilter #2).
    for (int idx = t; idx < 17 * SM_A; idx += 256) {
        int pair = idx / SM_A;           // 0..16
        int j = idx - pair * SM_A;       // 0..33 (apron col)
        int i0 = 2 * pair, i1 = i0 + 1;

        int py0 = min(max(gy0 - 1 + i0, 0), H_LR - 1);
        int py1 = min(max(gy0 - 1 + i1, 0), H_LR - 1);
        int si0 = py0 - gy0 + 2;         // [1,34]
        int si1 = py1 - gy0 + 2;
        int px = min(max(gx0 - 1 + j, 0), W_LR - 1);
        int sj = px - gx0 + 2;           // [1,34]

        // 4 tap rows: si0-1, si0, si0+1, si1+1
        float rsx[4], rsy[4], rsxy[4], rsxx[4];
        #pragma unroll
        for (int r = 0; r < 4; r++) {
            int row = (r < 3) ? (si0 - 1 + r) : (si1 + 1);
            float xs = 0.f, ys = 0.f, xys = 0.f, xxs = 0.f;
            #pragma unroll
            for (int c = -1; c <= 1; c++) {
                float xv = sx[row * SSTR + sj + c];
                float yv = sy[row * SSTR + sj + c];
                xs += xv; ys += yv;
                xys = fmaf(xv, yv, xys);
                xxs = fmaf(xv, xv, xxs);
            }
            rsx[r] = xs; rsy[r] = ys; rsxy[r] = xys; rsxx[r] = xxs;
        }

        bool two = (si1 != si0);
        float s0x  = rsx[0] + rsx[1] + rsx[2];
        float s0y  = rsy[0] + rsy[1] + rsy[2];
        float s0xy = rsxy[0] + rsxy[1] + rsxy[2];
        float s0xx = rsxx[0] + rsxx[1] + rsxx[2];
        float s1x  = two ? (rsx[1] + rsx[2] + rsx[3])   : s0x;
        float s1y  = two ? (rsy[1] + rsy[2] + rsy[3])   : s0y;
        float s1xy = two ? (rsxy[1] + rsxy[2] + rsxy[3]) : s0xy;
        float s1xx = two ? (rsxx[1] + rsxx[2] + rsxx[3]) : s0xx;

        float mx0 = s0x * inv9, my0 = s0y * inv9;
        float cov0 = s0xy * inv9 - mx0 * my0;
        float var0 = s0xx * inv9 - mx0 * mx0;
        float A0 = __fdividef(cov0, var0 + EPS_F);
        float B0 = my0 - A0 * mx0;

        float mx1 = s1x * inv9, my1 = s1y * inv9;
        float cov1 = s1xy * inv9 - mx1 * my1;
        float var1 = s1xx * inv9 - mx1 * mx1;
        float A1 = __fdividef(cov1, var1 + EPS_F);
        float B1 = my1 - A1 * mx1;

        sA[i0 * SSTR + j] = A0;
        sB[i0 * SSTR + j] = B0;
        sA[i1 * SSTR + j] = A1;
        sB[i1 * SSTR + j] = B1;
    }
    __syncthreads();

    // Phase 3a: horizontal 3-tap over A/b, store into reused sx/sy
    for (int idx = t; idx < SM_A * TILE; idx += 256) {
        int i = idx / TILE, j = idx - i * TILE;
        int o = i * SSTR + j;
        sx[o] = sA[o] + sA[o + 1] + sA[o + 2];
        sy[o] = sB[o] + sB[o + 1] + sB[o + 2];
    }
    __syncthreads();

    // Phase 3b: vertical 3-tap -> mean_A, mean_b, write to scratch
    const int tx = threadIdx.x;
    for (int ty = threadIdx.y; ty < TILE; ty += 8) {
        float sa = (sx[ty * SSTR + tx] + sx[(ty + 1) * SSTR + tx] + sx[(ty + 2) * SSTR + tx]) * inv9;
        float sb = (sy[ty * SSTR + tx] + sy[(ty + 1) * SSTR + tx] + sy[(ty + 2) * SSTR + tx]) * inv9;
        int o = plane * (H_LR * W_LR) + (gy0 + ty) * W_LR + (gx0 + tx);
        g_meanA[o] = sa;
        g_meanB[o] = sb;
    }
}

// Kernel 2: one block per output row. Stage vertically-lerped Ac/Bc (512 each)
// in SMEM; each thread handles 8 consecutive pixels spanning < 3 low-res
// units. Horizontal lerp is branch/select-free via the piecewise-linear
// closed form  aV(p) = A0 + D0*sat(p) + D1*sat(p-1) + D2*sat(p-2).
// Both x_hr float4 loads are issued up front (MLP=2).
__global__ __launch_bounds__(256)
void k2_upsample_apply(const float* __restrict__ xhr, float* __restrict__ out) {
    __shared__ float sAc[W_LR];
    __shared__ float sBc[W_LR];

    const float SCALE = 511.0f / 2047.0f;
    const int plane = blockIdx.y;
    const int oy = blockIdx.x;
    const int t = threadIdx.x;

    float posy = (float)oy * SCALE;
    int iy0 = (int)posy;
    float tyf = posy - (float)iy0;
    int iy1 = min(iy0 + 1, H_LR - 1);

    const size_t pl = (size_t)plane * (H_LR * W_LR);
    if (t < 128) {
        const float4* r0 = (const float4*)(g_meanA + pl + iy0 * W_LR);
        const float4* r1 = (const float4*)(g_meanA + pl + iy1 * W_LR);
        float4 a0 = r0[t], a1 = r1[t];
        float4 ac;
        ac.x = fmaf(tyf, a1.x - a0.x, a0.x);
        ac.y = fmaf(tyf, a1.y - a0.y, a0.y);
        ac.z = fmaf(tyf, a1.z - a0.z, a0.z);
        ac.w = fmaf(tyf, a1.w - a0.w, a0.w);
        ((float4*)sAc)[t] = ac;
    } else {
        int u = t - 128;
        const float4* r0 = (const float4*)(g_meanB + pl + iy0 * W_LR);
        const float4* r1 = (const float4*)(g_meanB + pl + iy1 * W_LR);
        float4 b0 = r0[u], b1 = r1[u];
        float4 bc;
        bc.x = fmaf(tyf, b1.x - b0.x, b0.x);
        bc.y = fmaf(tyf, b1.y - b0.y, b0.y);
        bc.z = fmaf(tyf, b1.z - b0.z, b0.z);
        bc.w = fmaf(tyf, b1.w - b0.w, b0.w);
        ((float4*)sBc)[u] = bc;
    }

    const size_t base = (size_t)plane * (H_HR * W_HR) + (size_t)oy * W_HR;
    const float4* __restrict__ xin4 = (const float4*)(xhr + base);
    float4* __restrict__ out4 = (float4*)(out + base);

    // Issue both global loads before touching smem results (MLP=2)
    const int q0 = t * 2;
    float4 xv0 = xin4[q0];
    float4 xv1 = xin4[q0 + 1];

    __syncthreads();

    const int ox0 = t * 8;
    float posx0 = (float)ox0 * SCALE;
    int jb = (int)posx0;
    float f0 = posx0 - (float)jb;          // in [0,1)

    int j3 = min(jb + 3, W_LR - 1);
    float A0 = sAc[jb], A1 = sAc[jb + 1], A2 = sAc[jb + 2], A3 = sAc[j3];
    float B0 = sBc[jb], B1 = sBc[jb + 1], B2 = sBc[jb + 2], B3 = sBc[j3];
    float DA0 = A1 - A0, DA1 = A2 - A1, DA2 = A3 - A2;
    float DB0 = B1 - B0, DB1 = B2 - B1, DB2 = B3 - B2;

    float xin[8] = {xv0.x, xv0.y, xv0.z, xv0.w, xv1.x, xv1.y, xv1.z, xv1.w};
    float res[8];
    #pragma unroll
    for (int k = 0; k < 8; k++) {
        float p = fmaf((float)k, SCALE, f0);   // in [0, 3)
        float t0 = __saturatef(p);
        float t1 = __saturatef(p - 1.0f);
        float t2 = __saturatef(p - 2.0f);
        float aV = fmaf(DA2, t2, fmaf(DA1, t1, fmaf(DA0, t0, A0)));
        float bV = fmaf(DB2, t2, fmaf(DB1, t1, fmaf(DB0, t0, B0)));
        float r = fmaf(aV, xin[k], bV);
        res[k] = fminf(fmaxf(r, 0.0f), 255.0f);
    }

    out4[q0]     = make_float4(res[0], res[1], res[2], res[3]);
    out4[q0 + 1] = make_float4(res[4], res[5], res[6], res[7]);
}

extern "C" void kernel_launch(void* const* d_in, const int* in_sizes, int n_in,
                              void* d_out, int out_size) {
    const float* x_lr = (const float*)d_in[0];
    const float* y_lr = (const float*)d_in[1];
    const float* x_hr = (const float*)d_in[2];
    float* out = (float*)d_out;

    dim3 g1(W_LR / TILE, H_LR / TILE, PLANES);   // (16,16,12)
    dim3 b1(32, 8);
    k1_ab_mean<<<g1, b1>>>(x_lr, y_lr);

    dim3 g2(H_HR, PLANES);                       // one block per output row
    k2_upsample_apply<<<g2, 256>>>(x_hr, out);
}

// round 8
// speedup vs baseline: 1.0201x; 1.0201x over previous
#include <cuda_runtime.h>

#define H_LR 512
#define W_LR 512
#define H_HR 2048
#define W_HR 2048
#define PLANES 12
#define EPS_F 0.01f

// Scratch for mean_A / mean_b at low resolution (alloc-free: __device__ globals)
__device__ float g_meanA[PLANES * H_LR * W_LR];
__device__ float g_meanB[PLANES * H_LR * W_LR];

#define TILE 32
#define SM_W 36   // TILE + 4 (2-pixel halo each side for double 3x3)
#define SM_A 34   // TILE + 2 (1-pixel apron of A/b)
#define SSTR 37   // row stride

__global__ __launch_bounds__(256)
void k1_ab_mean(const float* __restrict__ x, const float* __restrict__ y) {
    __shared__ float sx[SM_W * SSTR];
    __shared__ float sy[SM_W * SSTR];
    __shared__ float sA[SM_A * SSTR];
    __shared__ float sB[SM_A * SSTR];

    const int plane = blockIdx.z;
    const int gy0 = blockIdx.y * TILE;
    const int gx0 = blockIdx.x * TILE;
    const float* __restrict__ xp = x + (size_t)plane * (H_LR * W_LR);
    const float* __restrict__ yp = y + (size_t)plane * (H_LR * W_LR);
    const int t = threadIdx.y * 32 + threadIdx.x;
    const float inv9 = 1.0f / 9.0f;

    // Phase 1: load 36x36 halo with edge clamp
    for (int idx = t; idx < SM_W * SM_W; idx += 256) {
        int i = idx / SM_W, j = idx - i * SM_W;
        int gy = min(max(gy0 - 2 + i, 0), H_LR - 1);
        int gx = min(max(gx0 - 2 + j, 0), W_LR - 1);
        sx[i * SSTR + j] = xp[gy * W_LR + gx];
        sy[i * SSTR + j] = yp[gy * W_LR + gx];
    }
    __syncthreads();

    // Phase 2: compute A,b on the 34x34 apron. TWO outputs per thread paired
    // VERTICALLY (apron rows 2p, 2p+1) so consecutive threads touch
    // consecutive smem columns -> conflict-free LDS. The two 3x3 windows
    // share 2 tap rows (4 distinct rows total). A/b are evaluated at CLAMPED
    // global pixel coords (== replication padding of A for boxfilter #2).
    for (int idx = t; idx < 17 * SM_A; idx += 256) {
        int pair = idx / SM_A;           // 0..16
        int j = idx - pair * SM_A;       // 0..33 (apron col)
        int i0 = 2 * pair, i1 = i0 + 1;

        int py0 = min(max(gy0 - 1 + i0, 0), H_LR - 1);
        int py1 = min(max(gy0 - 1 + i1, 0), H_LR - 1);
        int si0 = py0 - gy0 + 2;         // [1,34]
        int si1 = py1 - gy0 + 2;
        int px = min(max(gx0 - 1 + j, 0), W_LR - 1);
        int sj = px - gx0 + 2;           // [1,34]

        // 4 tap rows: si0-1, si0, si0+1, si1+1
        float rsx[4], rsy[4], rsxy[4], rsxx[4];
        #pragma unroll
        for (int r = 0; r < 4; r++) {
            int row = (r < 3) ? (si0 - 1 + r) : (si1 + 1);
            float xs = 0.f, ys = 0.f, xys = 0.f, xxs = 0.f;
            #pragma unroll
            for (int c = -1; c <= 1; c++) {
                float xv = sx[row * SSTR + sj + c];
                float yv = sy[row * SSTR + sj + c];
                xs += xv; ys += yv;
                xys = fmaf(xv, yv, xys);
                xxs = fmaf(xv, xv, xxs);
            }
            rsx[r] = xs; rsy[r] = ys; rsxy[r] = xys; rsxx[r] = xxs;
        }

        bool two = (si1 != si0);
        float s0x  = rsx[0] + rsx[1] + rsx[2];
        float s0y  = rsy[0] + rsy[1] + rsy[2];
        float s0xy = rsxy[0] + rsxy[1] + rsxy[2];
        float s0xx = rsxx[0] + rsxx[1] + rsxx[2];
        float s1x  = two ? (rsx[1] + rsx[2] + rsx[3])   : s0x;
        float s1y  = two ? (rsy[1] + rsy[2] + rsy[3])   : s0y;
        float s1xy = two ? (rsxy[1] + rsxy[2] + rsxy[3]) : s0xy;
        float s1xx = two ? (rsxx[1] + rsxx[2] + rsxx[3]) : s0xx;

        float mx0 = s0x * inv9, my0 = s0y * inv9;
        float cov0 = s0xy * inv9 - mx0 * my0;
        float var0 = s0xx * inv9 - mx0 * mx0;
        float A0 = __fdividef(cov0, var0 + EPS_F);
        float B0 = my0 - A0 * mx0;

        float mx1 = s1x * inv9, my1 = s1y * inv9;
        float cov1 = s1xy * inv9 - mx1 * my1;
        float var1 = s1xx * inv9 - mx1 * mx1;
        float A1 = __fdividef(cov1, var1 + EPS_F);
        float B1 = my1 - A1 * mx1;

        sA[i0 * SSTR + j] = A0;
        sB[i0 * SSTR + j] = B0;
        sA[i1 * SSTR + j] = A1;
        sB[i1 * SSTR + j] = B1;
    }
    __syncthreads();

    // Phase 3a: horizontal 3-tap over A/b, store into reused sx/sy
    for (int idx = t; idx < SM_A * TILE; idx += 256) {
        int i = idx / TILE, j = idx - i * TILE;
        int o = i * SSTR + j;
        sx[o] = sA[o] + sA[o + 1] + sA[o + 2];
        sy[o] = sB[o] + sB[o + 1] + sB[o + 2];
    }
    __syncthreads();

    // Phase 3b: vertical 3-tap -> mean_A, mean_b, write to scratch
    const int tx = threadIdx.x;
    for (int ty = threadIdx.y; ty < TILE; ty += 8) {
        float sa = (sx[ty * SSTR + tx] + sx[(ty + 1) * SSTR + tx] + sx[(ty + 2) * SSTR + tx]) * inv9;
        float sb = (sy[ty * SSTR + tx] + sy[(ty + 1) * SSTR + tx] + sy[(ty + 2) * SSTR + tx]) * inv9;
        int o = plane * (H_LR * W_LR) + (gy0 + ty) * W_LR + (gx0 + tx);
        g_meanA[o] = sa;
        g_meanB[o] = sb;
    }
}

// Kernel 2: one block per output row. Stage vertically-lerped Ac/Bc (512 each)
// in SMEM; each thread handles 8 consecutive pixels spanning < 3 low-res
// units. Horizontal lerp is branch/select-free via the piecewise-linear
// closed form  aV(p) = A0 + D0*sat(p) + D1*sat(p-1) + D2*sat(p-2).
// Both x_hr float4 loads are issued up front (MLP=2).
__global__ __launch_bounds__(256)
void k2_upsample_apply(const float* __restrict__ xhr, float* __restrict__ out) {
    __shared__ float sAc[W_LR];
    __shared__ float sBc[W_LR];

    const float SCALE = 511.0f / 2047.0f;
    const int plane = blockIdx.y;
    const int oy = blockIdx.x;
    const int t = threadIdx.x;

    float posy = (float)oy * SCALE;
    int iy0 = (int)posy;
    float tyf = posy - (float)iy0;
    int iy1 = min(iy0 + 1, H_LR - 1);

    const size_t pl = (size_t)plane * (H_LR * W_LR);
    if (t < 128) {
        const float4* r0 = (const float4*)(g_meanA + pl + iy0 * W_LR);
        const float4* r1 = (const float4*)(g_meanA + pl + iy1 * W_LR);
        float4 a0 = r0[t], a1 = r1[t];
        float4 ac;
        ac.x = fmaf(tyf, a1.x - a0.x, a0.x);
        ac.y = fmaf(tyf, a1.y - a0.y, a0.y);
        ac.z = fmaf(tyf, a1.z - a0.z, a0.z);
        ac.w = fmaf(tyf, a1.w - a0.w, a0.w);
        ((float4*)sAc)[t] = ac;
    } else {
        int u = t - 128;
        const float4* r0 = (const float4*)(g_meanB + pl + iy0 * W_LR);
        const float4* r1 = (const float4*)(g_meanB + pl + iy1 * W_LR);
        float4 b0 = r0[u], b1 = r1[u];
        float4 bc;
        bc.x = fmaf(tyf, b1.x - b0.x, b0.x);
        bc.y = fmaf(tyf, b1.y - b0.y, b0.y);
        bc.z = fmaf(tyf, b1.z - b0.z, b0.z);
        bc.w = fmaf(tyf, b1.w - b0.w, b0.w);
        ((float4*)sBc)[u] = bc;
    }

    const size_t base = (size_t)plane * (H_HR * W_HR) + (size_t)oy * W_HR;
    const float4* __restrict__ xin4 = (const float4*)(xhr + base);
    float4* __restrict__ out4 = (float4*)(out + base);

    // Issue both global loads before touching smem results (MLP=2)
    const int q0 = t * 2;
    float4 xv0 = xin4[q0];
    float4 xv1 = xin4[q0 + 1];

    __syncthreads();

    const int ox0 = t * 8;
    float posx0 = (float)ox0 * SCALE;
    int jb = (int)posx0;
    float f0 = posx0 - (float)jb;          // in [0,1)

    int j3 = min(jb + 3, W_LR - 1);
    float A0 = sAc[jb], A1 = sAc[jb + 1], A2 = sAc[jb + 2], A3 = sAc[j3];
    float B0 = sBc[jb], B1 = sBc[jb + 1], B2 = sBc[jb + 2], B3 = sBc[j3];
    float DA0 = A1 - A0, DA1 = A2 - A1, DA2 = A3 - A2;
    float DB0 = B1 - B0, DB1 = B2 - B1, DB2 = B3 - B2;

    float xin[8] = {xv0.x, xv0.y, xv0.z, xv0.w, xv1.x, xv1.y, xv1.z, xv1.w};
    float res[8];
    #pragma unroll
    for (int k = 0; k < 8; k++) {
        float p = fmaf((float)k, SCALE, f0);   // in [0, 3)
        float t0 = __saturatef(p);
        float t1 = __saturatef(p - 1.0f);
        float t2 = __saturatef(p - 2.0f);
        float aV = fmaf(DA2, t2, fmaf(DA1, t1, fmaf(DA0, t0, A0)));
        float bV = fmaf(DB2, t2, fmaf(DB1, t1, fmaf(DB0, t0, B0)));
        float r = fmaf(aV, xin[k], bV);
        res[k] = fminf(fmaxf(r, 0.0f), 255.0f);
    }

    out4[q0]     = make_float4(res[0], res[1], res[2], res[3]);
    out4[q0 + 1] = make_float4(res[4], res[5], res[6], res[7]);
}

extern "C" void kernel_launch(void* const* d_in, const int* in_sizes, int n_in,
                              void* d_out, int out_size) {
    const float* x_lr = (const float*)d_in[0];
    const float* y_lr = (const float*)d_in[1];
    const float* x_hr = (const float*)d_in[2];
    float* out = (float*)d_out;

    dim3 g1(W_LR / TILE, H_LR / TILE, PLANES);   // (16,16,12)
    dim3 b1(32, 8);
    k1_ab_mean<<<g1, b1>>>(x_lr, y_lr);

    dim3 g2(H_HR, PLANES);                       // one block per output row
    k2_upsample_apply<<<g2, 256>>>(x_hr, out);
}

// round 9
// speedup vs baseline: 1.0207x; 1.0006x over previous
#include <cuda_runtime.h>

#define H_LR 512
#define W_LR 512
#define H_HR 2048
#define W_HR 2048
#define PLANES 12
#define EPS_F 0.01f

// Scratch for mean_A / mean_b at low resolution (alloc-free: __device__ globals)
__device__ float g_meanA[PLANES * H_LR * W_LR];
__device__ float g_meanB[PLANES * H_LR * W_LR];

// k1 tile: 16 rows x 32 cols -> 6144 blocks (vs 768), full thread occupancy.
#define TW 32     // tile width (cols)
#define TH 16     // tile height (rows)
#define SMW_R 20  // TH + 4 halo rows
#define SMW_C 36  // TW + 4 halo cols
#define SMA_R 18  // TH + 2 apron rows
#define SMA_C 34  // TW + 2 apron cols
#define SSTR 37   // smem row stride

__global__ __launch_bounds__(256)
void k1_ab_mean(const float* __restrict__ x, const float* __restrict__ y) {
    __shared__ float sx[SMW_R * SSTR];
    __shared__ float sy[SMW_R * SSTR];
    __shared__ float sA[SMA_R * SSTR];
    __shared__ float sB[SMA_R * SSTR];

    const int plane = blockIdx.z;
    const int gy0 = blockIdx.y * TH;
    const int gx0 = blockIdx.x * TW;
    const float* __restrict__ xp = x + (size_t)plane * (H_LR * W_LR);
    const float* __restrict__ yp = y + (size_t)plane * (H_LR * W_LR);
    const int t = threadIdx.x;
    const float inv9 = 1.0f / 9.0f;

    // Phase 1: load 20x36 halo with edge clamp
    for (int idx = t; idx < SMW_R * SMW_C; idx += 256) {
        int i = idx / SMW_C, j = idx - i * SMW_C;
        int gy = min(max(gy0 - 2 + i, 0), H_LR - 1);
        int gx = min(max(gx0 - 2 + j, 0), W_LR - 1);
        sx[i * SSTR + j] = xp[gy * W_LR + gx];
        sy[i * SSTR + j] = yp[gy * W_LR + gx];
    }
    __syncthreads();

    // Phase 2: compute A,b on the 18x34 apron. TWO outputs per thread paired
    // VERTICALLY (apron rows 2p, 2p+1): consecutive threads touch consecutive
    // smem columns (conflict-free), windows share 2 of 4 tap rows. A/b are
    // evaluated at CLAMPED global coords (== replication padding of A).
    for (int idx = t; idx < 9 * SMA_C; idx += 256) {
        int pair = idx / SMA_C;          // 0..8
        int j = idx - pair * SMA_C;      // 0..33
        int i0 = 2 * pair, i1 = i0 + 1;

        int py0 = min(max(gy0 - 1 + i0, 0), H_LR - 1);
        int py1 = min(max(gy0 - 1 + i1, 0), H_LR - 1);
        int si0 = py0 - gy0 + 2;         // [1,18]
        int si1 = py1 - gy0 + 2;
        int px = min(max(gx0 - 1 + j, 0), W_LR - 1);
        int sj = px - gx0 + 2;           // [1,34]

        float rsx[4], rsy[4], rsxy[4], rsxx[4];
        #pragma unroll
        for (int r = 0; r < 4; r++) {
            int row = (r < 3) ? (si0 - 1 + r) : (si1 + 1);
            float xs = 0.f, ys = 0.f, xys = 0.f, xxs = 0.f;
            #pragma unroll
            for (int c = -1; c <= 1; c++) {
                float xv = sx[row * SSTR + sj + c];
                float yv = sy[row * SSTR + sj + c];
                xs += xv; ys += yv;
                xys = fmaf(xv, yv, xys);
                xxs = fmaf(xv, xv, xxs);
            }
            rsx[r] = xs; rsy[r] = ys; rsxy[r] = xys; rsxx[r] = xxs;
        }

        bool two = (si1 != si0);
        float s0x  = rsx[0] + rsx[1] + rsx[2];
        float s0y  = rsy[0] + rsy[1] + rsy[2];
        float s0xy = rsxy[0] + rsxy[1] + rsxy[2];
        float s0xx = rsxx[0] + rsxx[1] + rsxx[2];
        float s1x  = two ? (rsx[1] + rsx[2] + rsx[3])   : s0x;
        float s1y  = two ? (rsy[1] + rsy[2] + rsy[3])   : s0y;
        float s1xy = two ? (rsxy[1] + rsxy[2] + rsxy[3]) : s0xy;
        float s1xx = two ? (rsxx[1] + rsxx[2] + rsxx[3]) : s0xx;

        float mx0 = s0x * inv9, my0 = s0y * inv9;
        float cov0 = s0xy * inv9 - mx0 * my0;
        float var0 = s0xx * inv9 - mx0 * mx0;
        float A0 = __fdividef(cov0, var0 + EPS_F);
        float B0 = my0 - A0 * mx0;

        float mx1 = s1x * inv9, my1 = s1y * inv9;
        float cov1 = s1xy * inv9 - mx1 * my1;
        float var1 = s1xx * inv9 - mx1 * mx1;
        float A1 = __fdividef(cov1, var1 + EPS_F);
        float B1 = my1 - A1 * mx1;

        sA[i0 * SSTR + j] = A0;
        sB[i0 * SSTR + j] = B0;
        sA[i1 * SSTR + j] = A1;
        sB[i1 * SSTR + j] = B1;
    }
    __syncthreads();

    // Phase 3a: horizontal 3-tap over A/b into reused sx/sy
    for (int idx = t; idx < SMA_R * TW; idx += 256) {
        int i = idx / TW, j = idx - i * TW;
        int o = i * SSTR + j;
        sx[o] = sA[o] + sA[o + 1] + sA[o + 2];
        sy[o] = sB[o] + sB[o + 1] + sB[o + 2];
    }
    __syncthreads();

    // Phase 3b: vertical 3-tap -> mean_A, mean_b (128B coalesced stores)
    const int tx = t & 31;
    const int ty0 = t >> 5;              // 0..7
    for (int r = ty0; r < TH; r += 8) {
        float sa = (sx[r * SSTR + tx] + sx[(r + 1) * SSTR + tx] + sx[(r + 2) * SSTR + tx]) * inv9;
        float sb = (sy[r * SSTR + tx] + sy[(r + 1) * SSTR + tx] + sy[(r + 2) * SSTR + tx]) * inv9;
        int o = plane * (H_LR * W_LR) + (gy0 + r) * W_LR + (gx0 + tx);
        g_meanA[o] = sa;
        g_meanB[o] = sb;
    }
}

// Kernel 2 (unchanged from round 8): one block per output row; staged
// vertically-lerped Ac/Bc in SMEM; 8 px/thread via select-free piecewise
// lerp; both x_hr float4 loads issued up front.
__global__ __launch_bounds__(256)
void k2_upsample_apply(const float* __restrict__ xhr, float* __restrict__ out) {
    __shared__ float sAc[W_LR];
    __shared__ float sBc[W_LR];

    const float SCALE = 511.0f / 2047.0f;
    const int plane = blockIdx.y;
    const int oy = blockIdx.x;
    const int t = threadIdx.x;

    float posy = (float)oy * SCALE;
    int iy0 = (int)posy;
    float tyf = posy - (float)iy0;
    int iy1 = min(iy0 + 1, H_LR - 1);

    const size_t pl = (size_t)plane * (H_LR * W_LR);
    if (t < 128) {
        const float4* r0 = (const float4*)(g_meanA + pl + iy0 * W_LR);
        const float4* r1 = (const float4*)(g_meanA + pl + iy1 * W_LR);
        float4 a0 = r0[t], a1 = r1[t];
        float4 ac;
        ac.x = fmaf(tyf, a1.x - a0.x, a0.x);
        ac.y = fmaf(tyf, a1.y - a0.y, a0.y);
        ac.z = fmaf(tyf, a1.z - a0.z, a0.z);
        ac.w = fmaf(tyf, a1.w - a0.w, a0.w);
        ((float4*)sAc)[t] = ac;
    } else {
        int u = t - 128;
        const float4* r0 = (const float4*)(g_meanB + pl + iy0 * W_LR);
        const float4* r1 = (const float4*)(g_meanB + pl + iy1 * W_LR);
        float4 b0 = r0[u], b1 = r1[u];
        float4 bc;
        bc.x = fmaf(tyf, b1.x - b0.x, b0.x);
        bc.y = fmaf(tyf, b1.y - b0.y, b0.y);
        bc.z = fmaf(tyf, b1.z - b0.z, b0.z);
        bc.w = fmaf(tyf, b1.w - b0.w, b0.w);
        ((float4*)sBc)[u] = bc;
    }

    const size_t base = (size_t)plane * (H_HR * W_HR) + (size_t)oy * W_HR;
    const float4* __restrict__ xin4 = (const float4*)(xhr + base);
    float4* __restrict__ out4 = (float4*)(out + base);

    const int q0 = t * 2;
    float4 xv0 = xin4[q0];
    float4 xv1 = xin4[q0 + 1];

    __syncthreads();

    const int ox0 = t * 8;
    float posx0 = (float)ox0 * SCALE;
    int jb = (int)posx0;
    float f0 = posx0 - (float)jb;

    int j3 = min(jb + 3, W_LR - 1);
    float A0 = sAc[jb], A1 = sAc[jb + 1], A2 = sAc[jb + 2], A3 = sAc[j3];
    float B0 = sBc[jb], B1 = sBc[jb + 1], B2 = sBc[jb + 2], B3 = sBc[j3];
    float DA0 = A1 - A0, DA1 = A2 - A1, DA2 = A3 - A2;
    float DB0 = B1 - B0, DB1 = B2 - B1, DB2 = B3 - B2;

    float xin[8] = {xv0.x, xv0.y, xv0.z, xv0.w, xv1.x, xv1.y, xv1.z, xv1.w};
    float res[8];
    #pragma unroll
    for (int k = 0; k < 8; k++) {
        float p = fmaf((float)k, SCALE, f0);
        float t0 = __saturatef(p);
        float t1 = __saturatef(p - 1.0f);
        float t2 = __saturatef(p - 2.0f);
        float aV = fmaf(DA2, t2, fmaf(DA1, t1, fmaf(DA0, t0, A0)));
        float bV = fmaf(DB2, t2, fmaf(DB1, t1, fmaf(DB0, t0, B0)));
        float r = fmaf(aV, xin[k], bV);
        res[k] = fminf(fmaxf(r, 0.0f), 255.0f);
    }

    out4[q0]     = make_float4(res[0], res[1], res[2], res[3]);
    out4[q0 + 1] = make_float4(res[4], res[5], res[6], res[7]);
}

extern "C" void kernel_launch(void* const* d_in, const int* in_sizes, int n_in,
                              void* d_out, int out_size) {
    const float* x_lr = (const float*)d_in[0];
    const float* y_lr = (const float*)d_in[1];
    const float* x_hr = (const float*)d_in[2];
    float* out = (float*)d_out;

    dim3 g1(W_LR / TW, H_LR / TH, PLANES);   // (16,32,12) = 6144 blocks
    k1_ab_mean<<<g1, 256>>>(x_lr, y_lr);

    dim3 g2(H_HR, PLANES);                   // one block per output row
    k2_upsample_apply<<<g2, 256>>>(x_hr, out);
}